// round 13
// baseline (speedup 1.0000x reference)
#include <cuda_runtime.h>
#include <cstdint>

#define B_ 4
#define L_ 512
#define D_ 256
#define U_ 64
#define TI 8
#define TJ 32

// scratch (static __device__ globals -- no allocation)
__device__ float g_q[B_*L_*U_];
__device__ float g_k[B_*L_*U_];
// flash-decoding partials: [b][it][seg][row][264] (acc 0..255, m @256, s @257)
__device__ float g_part[4][64][4][8][264];

__device__ __forceinline__ float tanh_ap(float x){ float y; asm("tanh.approx.f32 %0, %1;" : "=f"(y) : "f"(x)); return y; }
__device__ __forceinline__ float ex2_ap(float x){ float y; asm("ex2.approx.f32 %0, %1;" : "=f"(y) : "f"(x)); return y; }
__device__ __forceinline__ unsigned long long dup2(float x){
    unsigned long long r; asm("mov.b64 %0, {%1, %1};" : "=l"(r) : "f"(x)); return r;
}
__device__ __forceinline__ void fma2(unsigned long long &a, unsigned long long x, unsigned long long y){
    asm("fma.rn.f32x2 %0, %1, %2, %0;" : "+l"(a) : "l"(x), "l"(y));
}
__device__ __forceinline__ void mul2(unsigned long long &a, unsigned long long x){
    asm("mul.rn.f32x2 %0, %0, %1;" : "+l"(a) : "l"(x));
}
__device__ __forceinline__ float2 unpack2(unsigned long long v){
    float lo, hi; asm("mov.b64 {%0, %1}, %2;" : "=f"(lo), "=f"(hi) : "l"(v)); return make_float2(lo, hi);
}
__device__ __forceinline__ unsigned smem_u32(const void* p){
    return (unsigned)__cvta_generic_to_shared(p);
}
__device__ __forceinline__ void cp16(unsigned dst, const void* src){
    asm volatile("cp.async.cg.shared.global [%0], [%1], 16;" :: "r"(dst), "l"(src));
}
__device__ __forceinline__ void cp_commit(){ asm volatile("cp.async.commit_group;"); }
__device__ __forceinline__ void cp_wait0(){ asm volatile("cp.async.wait_group 0;"); }
__device__ __forceinline__ void cp_wait1(){ asm volatile("cp.async.wait_group 1;"); }
__device__ __forceinline__ void cp_wait2(){ asm volatile("cp.async.wait_group 2;"); }

// ---------------------------------------------------------------------------
// Phase 1: q = X@Wt ; k = X@Wx + bh.  128 blocks x 256 threads, 32 rows/block.
// (unchanged from R10 -- measured improvement)
// ---------------------------------------------------------------------------
__global__ void __launch_bounds__(256) proj_kernel(
    const float* __restrict__ X, const float* __restrict__ Wt,
    const float* __restrict__ Wx, const float* __restrict__ bh)
{
    extern __shared__ __align__(16) float psm[];
    float* W_s = psm;            // 64KB
    float* x_s = psm + 16384;    // 32KB

    const int bid  = blockIdx.x;
    const bool is_k = bid >= 64;
    const int rb   = bid & 63;
    const float* __restrict__ W = is_k ? Wx : Wt;
    const int t    = threadIdx.x;
    const int row0 = rb * 32;

    const float4* W4 = reinterpret_cast<const float4*>(W);
    const float4* X4 = reinterpret_cast<const float4*>(X) + row0*(D_/4);
    for (int i = t; i < (D_*U_)/4; i += 256) reinterpret_cast<float4*>(W_s)[i] = W4[i];
    for (int i = t; i < (32*D_)/4;  i += 256) reinterpret_cast<float4*>(x_s)[i] = X4[i];
    __syncthreads();

    const int quad = t & 15;
    const int r    = t >> 4;
    const float4* xa4 = reinterpret_cast<const float4*>(x_s) + r*(D_/4);
    const float4* xb4 = reinterpret_cast<const float4*>(x_s) + (r+16)*(D_/4);

    unsigned long long a01_0 = 0ull, a23_0 = 0ull;
    unsigned long long a01_1 = 0ull, a23_1 = 0ull;

    #pragma unroll 2
    for (int d4 = 0; d4 < D_/4; ++d4) {
        float4 xa = xa4[d4];
        float4 xb = xb4[d4];
        const float* xaf = reinterpret_cast<const float*>(&xa);
        const float* xbf = reinterpret_cast<const float*>(&xb);
        #pragma unroll
        for (int c = 0; c < 4; ++c) {
            ulonglong2 w2 = *reinterpret_cast<const ulonglong2*>(W_s + (d4*4+c)*U_ + quad*4);
            unsigned long long xx0 = dup2(xaf[c]);
            unsigned long long xx1 = dup2(xbf[c]);
            fma2(a01_0, xx0, w2.x);
            fma2(a23_0, xx0, w2.y);
            fma2(a01_1, xx1, w2.x);
            fma2(a23_1, xx1, w2.y);
        }
    }

    float bx = 0.f, by = 0.f, bz = 0.f, bw = 0.f;
    if (is_k) { bx = bh[quad*4+0]; by = bh[quad*4+1]; bz = bh[quad*4+2]; bw = bh[quad*4+3]; }

    float* base = (is_k ? g_k : g_q);
    {
        float2 v01 = unpack2(a01_0), v23 = unpack2(a23_0);
        float4 o; o.x = v01.x+bx; o.y = v01.y+by; o.z = v23.x+bz; o.w = v23.y+bw;
        *reinterpret_cast<float4*>(base + (row0 + r)*U_ + quad*4) = o;
    }
    {
        float2 v01 = unpack2(a01_1), v23 = unpack2(a23_1);
        float4 o; o.x = v01.x+bx; o.y = v01.y+by; o.z = v23.x+bz; o.w = v23.y+bw;
        *reinterpret_cast<float4*>(base + (row0 + r + 16)*U_ + quad*4) = o;
    }
}

// ---------------------------------------------------------------------------
// Phase 2a: flash-decoding partials. 640 CTAs x 256 threads, 3 CTAs/SM.
// CTA = (batch b, row-tile it, segment s of <=4 j-tiles).
// it<16 (single segment) writes output directly; else flushes (m,s,acc).
// k double-buffered cp.async; X single-buffered, fill hidden under score via
// wait_group(2)->(1) choreography. Sum-shuffle overlapped with PV.
// smem: kbuf 16K | Xs 32K | q 2K | wa 256 | p2(dup) 2K | alpha 32 | pm/ps 64
// ---------------------------------------------------------------------------
__global__ void __launch_bounds__(256, 3) attn_partial(
    const float* __restrict__ X, const float* __restrict__ Wa,
    float* __restrict__ out)
{
    extern __shared__ __align__(16) unsigned char smem_raw[];
    float4* kbuf   = reinterpret_cast<float4*>(smem_raw);                   // 16KB (2 bufs)
    float*  Xs     = reinterpret_cast<float*>(smem_raw + 16384);            // 32KB
    float4* q_s    = reinterpret_cast<float4*>(smem_raw + 16384 + 32768);   // 2KB
    float4* wa4    = reinterpret_cast<float4*>(smem_raw + 51200);           // 256B
    float2* p2     = reinterpret_cast<float2*>(smem_raw + 51456);           // 2KB (dup pairs)
    float*  alpha_s= reinterpret_cast<float*>(smem_raw + 53504);            // 32B
    float*  pm     = reinterpret_cast<float*>(smem_raw + 53536);            // 32B
    float*  ps     = reinterpret_cast<float*>(smem_raw + 53568);            // 32B

    const int t    = threadIdx.x;
    const int lane = t & 31;
    const int w    = t >> 5;                 // warp = row 0..7

    // decode CTA -> (b, it, s); LPT: large row-tiles (most segments) first
    const int b   = blockIdx.x & 3;
    const int sid = 159 - (blockIdx.x >> 2);
    int it, s;
    if      (sid < 16) { it = sid;                 s = 0; }
    else if (sid < 48) { it = 16 + (sid-16)/2;     s = (sid-16)%2; }
    else if (sid < 96) { it = 32 + (sid-48)/3;     s = (sid-48)%3; }
    else               { it = 48 + (sid-96)/4;     s = (sid-96)%4; }

    const int i0   = it * TI;
    const int ntj  = it/4 + 1;
    const int t0   = s*4;
    const int t1   = (t0 + 4 < ntj) ? (t0 + 4) : ntj;
    const bool single = (it < 16);           // one segment -> direct output

    const float* __restrict__ Xb = X   + b*L_*D_;
    const float* __restrict__ kb = g_k + b*L_*U_;
    const float* __restrict__ qb = g_q + b*L_*U_;

    if (t < U_) reinterpret_cast<float*>(wa4)[t] = Wa[t] * 1.4426950408889634f;
    if (t < 128) {
        int i = t >> 4, uq = t & 15;
        q_s[uq*8 + i] = *reinterpret_cast<const float4*>(qb + (i0+i)*U_ + uq*4);
    }

    // cp.async targets
    const int kf_uq0 = t & 15,        kf_j0 = t >> 4;
    const int kf_uq1 = (t+256) & 15,  kf_j1 = (t+256) >> 4;
    const unsigned k_dst0 = smem_u32(kbuf) + (kf_uq0*TJ + kf_j0)*16;
    const unsigned k_dst1 = smem_u32(kbuf) + (kf_uq1*TJ + kf_j1)*16;
    const unsigned x_dst0 = smem_u32(Xs) + t*16;
    const unsigned KBUF_B = 512*16;

    // prologue: commit k(t0) into buffer (t0&1)
    {
        const int j0p = t0*TJ;
        const unsigned off = (t0 & 1)*KBUF_B;
        cp16(k_dst0 + off, kb + (j0p + kf_j0)*U_ + kf_uq0*4);
        cp16(k_dst1 + off, kb + (j0p + kf_j1)*U_ + kf_uq1*4);
        cp_commit();
    }

    float m_run = -1e30f, s_run = 0.f;
    unsigned long long a0l = 0ull, a0h = 0ull, a1l = 0ull, a1h = 0ull;
    const int gi = i0 + w;

    const int dq = t & 63;             // d-quad
    const int rp = t >> 6;             // row pair
    const int lr0 = 2*rp, lr1 = 2*rp + 1;

    for (int n = t0; n < t1; ++n) {
        const int j0  = n * TJ;
        const int cur = n & 1;
        const bool more = (n + 1 < t1);

        __syncthreads();   // prev PV done with Xs/p2 (first iter: orders q/wa stores)

        // commit X(n) fill
        #pragma unroll
        for (int rep = 0; rep < 8; ++rep) {
            int idx = t + rep*256;
            cp16(x_dst0 + rep*4096, Xb + (j0 + (idx>>6))*D_ + (idx&63)*4);
        }
        cp_commit();
        // commit k(n+1) fill
        if (more) {
            const int j0n = j0 + TJ;
            const unsigned off = ((n+1) & 1)*KBUF_B;
            cp16(k_dst0 + off, kb + (j0n + kf_j0)*U_ + kf_uq0*4);
            cp16(k_dst1 + off, kb + (j0n + kf_j1)*U_ + kf_uq1*4);
            cp_commit();
        }
        if (more) cp_wait2(); else cp_wait1();   // k(n) landed
        __syncthreads();                         // k(n) visible CTA-wide

        // ---- score: e[gi][j0+lane] in log2 domain ----
        const float4* kc = kbuf + cur*512;
        float e0 = 0.f, e1 = 0.f;
        #pragma unroll
        for (int uq = 0; uq < 16; ++uq) {
            float4 kv = kc[uq*TJ + lane];    // conflict-free
            float4 qv = q_s[uq*8 + w];       // broadcast
            float4 wa = wa4[uq];             // broadcast
            e0 += wa.x * tanh_ap(qv.x + kv.x);
            e1 += wa.y * tanh_ap(qv.y + kv.y);
            e0 += wa.z * tanh_ap(qv.z + kv.z);
            e1 += wa.w * tanh_ap(qv.w + kv.w);
        }
        float e = e0 + e1;
        if (j0 + lane > gi) e = -1e30f;      // causal: exp2 -> exact 0

        // ---- max + p (sum deferred past barrier) ----
        float mt = e;
        #pragma unroll
        for (int off = 16; off; off >>= 1)
            mt = fmaxf(mt, __shfl_xor_sync(0xffffffffu, mt, off));
        float m_new = fmaxf(m_run, mt);
        float p     = ex2_ap(e - m_new);
        float alpha = ex2_ap(m_run - m_new);
        p2[w*TJ + lane] = make_float2(p, p);     // pre-duplicated (STS.64)
        if (lane == 0) alpha_s[w] = alpha;

        if (more) cp_wait1(); else cp_wait0();   // X(n) landed (k(n+1) may pend)
        __syncthreads();                         // X + p2 + alpha visible

        // sum reduction overlaps PV below
        float st = p;
        #pragma unroll
        for (int off = 16; off; off >>= 1)
            st += __shfl_xor_sync(0xffffffffu, st, off);
        s_run = s_run * alpha + st;
        m_run = m_new;

        // ---- PV: 4 d x 2 rows per thread, packed f32x2 ----
        {
            unsigned long long al0 = dup2(alpha_s[lr0]);
            unsigned long long al1 = dup2(alpha_s[lr1]);
            mul2(a0l, al0); mul2(a0h, al0);
            mul2(a1l, al1); mul2(a1h, al1);
        }
        const ulonglong2* X2 = reinterpret_cast<const ulonglong2*>(Xs);
        const unsigned long long* p0d = reinterpret_cast<const unsigned long long*>(&p2[lr0*TJ]);
        const unsigned long long* p1d = reinterpret_cast<const unsigned long long*>(&p2[lr1*TJ]);
        #pragma unroll
        for (int jc = 0; jc < TJ/4; ++jc) {
            #pragma unroll
            for (int j = 0; j < 4; ++j) {
                ulonglong2 xv = X2[(jc*4 + j)*(D_/4) + dq];   // packed (xlo,xhi)
                unsigned long long d0 = p0d[jc*4 + j];        // broadcast dup pair
                unsigned long long d1 = p1d[jc*4 + j];
                fma2(a0l, xv.x, d0); fma2(a0h, xv.y, d0);
                fma2(a1l, xv.x, d1); fma2(a1h, xv.y, d1);
            }
        }
    }

    // ---- epilogue ----
    if (lane == 0) { pm[w] = m_run; ps[w] = s_run; }
    __syncthreads();

    if (single) {
        const float is0 = 1.0f / ps[lr0];
        const float is1 = 1.0f / ps[lr1];
        float2 vl = unpack2(a0l), vh = unpack2(a0h);
        float4 o0; o0.x = vl.x*is0; o0.y = vl.y*is0; o0.z = vh.x*is0; o0.w = vh.y*is0;
        *reinterpret_cast<float4*>(out + (b*L_ + i0 + lr0)*D_ + dq*4) = o0;
        vl = unpack2(a1l); vh = unpack2(a1h);
        float4 o1; o1.x = vl.x*is1; o1.y = vl.y*is1; o1.z = vh.x*is1; o1.w = vh.y*is1;
        *reinterpret_cast<float4*>(out + (b*L_ + i0 + lr1)*D_ + dq*4) = o1;
    } else {
        float* dst0 = &g_part[b][it][s][lr0][0];
        float* dst1 = &g_part[b][it][s][lr1][0];
        float2 vl = unpack2(a0l), vh = unpack2(a0h);
        float4 f0; f0.x = vl.x; f0.y = vl.y; f0.z = vh.x; f0.w = vh.y;
        *reinterpret_cast<float4*>(dst0 + dq*4) = f0;
        vl = unpack2(a1l); vh = unpack2(a1h);
        float4 f1; f1.x = vl.x; f1.y = vl.y; f1.z = vh.x; f1.w = vh.y;
        *reinterpret_cast<float4*>(dst1 + dq*4) = f1;
        if (t < 8) {
            g_part[b][it][s][t][256] = pm[t];
            g_part[b][it][s][t][257] = ps[t];
        }
    }
}

// ---------------------------------------------------------------------------
// Phase 2b: merge partials for row-tiles with >=2 segments (it >= 16).
// 192 CTAs x 256 threads; thread -> (row t>>5, 8 d's).
// ---------------------------------------------------------------------------
__global__ void __launch_bounds__(256) merge_kernel(float* __restrict__ out)
{
    const int b  = blockIdx.x & 3;
    const int it = 16 + (blockIdx.x >> 2);
    const int nseg = it/16 + 1;              // 2..4
    const int t  = threadIdx.x;
    const int r  = t >> 5;
    const int c  = t & 31;                   // d block: d = c*8 .. +7

    float m[4], sv[4];
    float M = -1e30f;
    for (int k = 0; k < nseg; ++k) {
        m[k]  = g_part[b][it][k][r][256];
        sv[k] = g_part[b][it][k][r][257];
        M = fmaxf(M, m[k]);
    }
    float den = 0.f, wgt[4];
    for (int k = 0; k < nseg; ++k) {
        wgt[k] = ex2_ap(m[k] - M);
        den += wgt[k]*sv[k];
    }
    const float dn = 1.0f / den;

    float4 o0 = make_float4(0,0,0,0), o1 = make_float4(0,0,0,0);
    for (int k = 0; k < nseg; ++k) {
        const float4* a = reinterpret_cast<const float4*>(&g_part[b][it][k][r][0]) + c*2;
        float4 c0 = a[0], c1 = a[1];
        float wk = wgt[k];
        o0.x += wk*c0.x; o0.y += wk*c0.y; o0.z += wk*c0.z; o0.w += wk*c0.w;
        o1.x += wk*c1.x; o1.y += wk*c1.y; o1.z += wk*c1.z; o1.w += wk*c1.w;
    }
    o0.x *= dn; o0.y *= dn; o0.z *= dn; o0.w *= dn;
    o1.x *= dn; o1.y *= dn; o1.z *= dn; o1.w *= dn;
    float4* dst = reinterpret_cast<float4*>(out + (b*L_ + it*TI + r)*D_ + c*8);
    dst[0] = o0; dst[1] = o1;
}

// ---------------------------------------------------------------------------
extern "C" void kernel_launch(void* const* d_in, const int* in_sizes, int n_in,
                              void* d_out, int out_size)
{
    const float* X  = (const float*)d_in[0];
    const float* Wt = (const float*)d_in[1];
    const float* Wx = (const float*)d_in[2];
    const float* bh = (const float*)d_in[3];
    const float* Wa = (const float*)d_in[4];
    // d_in[5] = ba : constant shift inside softmax -> mathematically a no-op

    const int proj_smem = (16384 + 8192) * 4;   // 96KB
    const int part_smem = 53600;                // ~52.3KB -> 3 CTAs/SM
    cudaFuncSetAttribute(proj_kernel,  cudaFuncAttributeMaxDynamicSharedMemorySize, proj_smem);
    cudaFuncSetAttribute(attn_partial, cudaFuncAttributeMaxDynamicSharedMemorySize, part_smem);

    proj_kernel<<<128, 256, proj_smem>>>(X, Wt, Wx, bh);
    attn_partial<<<640, 256, part_smem>>>(X, Wa, (float*)d_out);
    merge_kernel<<<192, 256>>>((float*)d_out);
}

// round 14
// speedup vs baseline: 1.2236x; 1.2236x over previous
#include <cuda_runtime.h>
#include <cstdint>

#define B_ 4
#define L_ 512
#define D_ 256
#define U_ 64
#define TI 8
#define TJ 32
#define NTROW (L_/TI)   // 64 row tiles per batch

// scratch for projections (allowed: __device__ globals, no allocation)
__device__ float g_q[B_*L_*U_];
__device__ float g_k[B_*L_*U_];

__device__ __forceinline__ float tanh_ap(float x){ float y; asm("tanh.approx.f32 %0, %1;" : "=f"(y) : "f"(x)); return y; }
__device__ __forceinline__ float ex2_ap(float x){ float y; asm("ex2.approx.f32 %0, %1;" : "=f"(y) : "f"(x)); return y; }
__device__ __forceinline__ unsigned long long dup2(float x){
    unsigned long long r; asm("mov.b64 %0, {%1, %1};" : "=l"(r) : "f"(x)); return r;
}
__device__ __forceinline__ void fma2(unsigned long long &a, unsigned long long x, unsigned long long y){
    asm("fma.rn.f32x2 %0, %1, %2, %0;" : "+l"(a) : "l"(x), "l"(y));
}
__device__ __forceinline__ void mul2(unsigned long long &a, unsigned long long x){
    asm("mul.rn.f32x2 %0, %0, %1;" : "+l"(a) : "l"(x));
}
__device__ __forceinline__ float2 unpack2(unsigned long long v){
    float lo, hi; asm("mov.b64 {%0, %1}, %2;" : "=f"(lo), "=f"(hi) : "l"(v)); return make_float2(lo, hi);
}
__device__ __forceinline__ unsigned smem_u32(const void* p){
    return (unsigned)__cvta_generic_to_shared(p);
}
__device__ __forceinline__ void cp16(unsigned dst, const void* src){
    asm volatile("cp.async.cg.shared.global [%0], [%1], 16;" :: "r"(dst), "l"(src));
}
__device__ __forceinline__ void cp_commit(){ asm volatile("cp.async.commit_group;"); }
__device__ __forceinline__ void cp_wait0(){ asm volatile("cp.async.wait_group 0;"); }
__device__ __forceinline__ void barg(int id){ asm volatile("bar.sync %0, 256;" :: "r"(id) : "memory"); }

// ---------------------------------------------------------------------------
// Phase 1 (REDESIGNED for latency): q = X@Wt ; k = X@Wx + bh.
// 256 blocks x 128 threads, 16 rows/block (2 rows/thread, 8 acc chains).
// W staged in two 32KB halves (static smem -> co-resident CTAs);
// X read directly via LDG.128 (L1 broadcast, no staging stage/syncs).
// ---------------------------------------------------------------------------
__global__ void __launch_bounds__(128) proj_kernel(
    const float* __restrict__ X, const float* __restrict__ Wt,
    const float* __restrict__ Wx, const float* __restrict__ bh)
{
    __shared__ __align__(16) float W_s[128*U_];   // 32KB (half of W)

    const int bid  = blockIdx.x;
    const bool is_k = bid >= 128;
    const int rb   = bid & 127;
    const float* __restrict__ W = is_k ? Wx : Wt;
    const int t    = threadIdx.x;
    const int row0 = rb * 16;

    const int quad = t & 15;     // u = quad*4 .. +3
    const int rg   = t >> 4;     // rows rg and rg+8

    const float4* __restrict__ Xa = reinterpret_cast<const float4*>(X + (row0+rg  )*D_);
    const float4* __restrict__ Xb = reinterpret_cast<const float4*>(X + (row0+rg+8)*D_);
    const float4* __restrict__ W4 = reinterpret_cast<const float4*>(W);

    unsigned long long a01_0 = 0ull, a23_0 = 0ull;
    unsigned long long a01_1 = 0ull, a23_1 = 0ull;

    #pragma unroll
    for (int half = 0; half < 2; ++half) {
        __syncthreads();
        #pragma unroll
        for (int i = 0; i < 16; ++i)      // 2048 float4 / 128 threads
            reinterpret_cast<float4*>(W_s)[t + i*128] = W4[half*2048 + t + i*128];
        __syncthreads();

        const int dbase = half * 32;      // in float4 units
        #pragma unroll 4
        for (int d4 = 0; d4 < 32; ++d4) {
            float4 xa = Xa[dbase + d4];   // LDG.128, L1-broadcast across quad group
            float4 xb = Xb[dbase + d4];
            const float* xaf = reinterpret_cast<const float*>(&xa);
            const float* xbf = reinterpret_cast<const float*>(&xb);
            #pragma unroll
            for (int c = 0; c < 4; ++c) {
                ulonglong2 w2 = *reinterpret_cast<const ulonglong2*>(W_s + (d4*4+c)*U_ + quad*4);
                unsigned long long xx0 = dup2(xaf[c]);
                unsigned long long xx1 = dup2(xbf[c]);
                fma2(a01_0, xx0, w2.x);
                fma2(a23_0, xx0, w2.y);
                fma2(a01_1, xx1, w2.x);
                fma2(a23_1, xx1, w2.y);
            }
        }
    }

    float bx = 0.f, by = 0.f, bz = 0.f, bw = 0.f;
    if (is_k) { bx = bh[quad*4+0]; by = bh[quad*4+1]; bz = bh[quad*4+2]; bw = bh[quad*4+3]; }

    float* base = (is_k ? g_k : g_q);
    {
        float2 v01 = unpack2(a01_0), v23 = unpack2(a23_0);
        float4 o; o.x = v01.x+bx; o.y = v01.y+by; o.z = v23.x+bz; o.w = v23.y+bw;
        *reinterpret_cast<float4*>(base + (row0 + rg)*U_ + quad*4) = o;
    }
    {
        float2 v01 = unpack2(a01_1), v23 = unpack2(a23_1);
        float4 o; o.x = v01.x+bx; o.y = v01.y+by; o.z = v23.x+bz; o.w = v23.y+bw;
        *reinterpret_cast<float4*>(base + (row0 + rg + 8)*U_ + quad*4) = o;
    }
}

// ---------------------------------------------------------------------------
// Phase 2: split-KV balanced dual-group attention (R9 = best measured 35.8us),
// with the redundant end-of-loop barrier removed (validated in R10).
// 128 CTAs x 512 threads. CTA -> row-tile pair {A=pr, B=63-pr}; 17 j-tile jobs
// split 9/8 between groups; B merged flash-decoding style in-kernel.
// ---------------------------------------------------------------------------
#define GRP_B (16384 + 65536)

__global__ void __launch_bounds__(512, 1) attn_kernel(
    const float* __restrict__ X, const float* __restrict__ Wa,
    float* __restrict__ out)
{
    extern __shared__ __align__(16) unsigned char smem_raw[];

    const int t    = threadIdx.x;
    const int g    = t >> 8;           // group 0/1
    const int tl   = t & 255;          // thread-in-group
    const int lane = t & 31;
    const int wl   = (t >> 5) & 7;     // warp-in-group
    const int b    = blockIdx.x >> 5;
    const int pr   = blockIdx.x & 31;

    const int i0A  = pr * TI;
    const int i0B  = (63 - pr) * TI;
    const int ntjA = pr/4 + 1;             // tiles for row-tile A (1..8)
    const int sB   = 9 - ntjA;             // group0's B tiles [0, sB)
    const int njobs = g ? 8 : 9;

    unsigned char* grp = smem_raw + g*GRP_B;
    float4* kbuf = reinterpret_cast<float4*>(grp);                 // 2x8KB
    float*  Xs   = reinterpret_cast<float*>(grp + 16384);          // 2x32KB
    unsigned char* tail = smem_raw + 2*GRP_B;
    float4* q_all  = reinterpret_cast<float4*>(tail);              // [rt*128+uq*8+i] 4KB
    float4* wa4    = reinterpret_cast<float4*>(tail + 4096);       // 256B
    float*  p4     = reinterpret_cast<float*>(tail + 4352) + g*256;
    float*  alpha_s= reinterpret_cast<float*>(tail + 6400) + g*8;
    float*  sinv   = reinterpret_cast<float*>(tail + 6464) + g*8;
    float*  paccb  = reinterpret_cast<float*>(tail + 6528);        // [g][8][256] 16KB
    float*  pacc   = paccb + g*2048;
    float*  pmb    = reinterpret_cast<float*>(tail + 6528 + 16384);// [g][8]
    float*  psb    = pmb + 16;
    float*  pm     = pmb + g*8;
    float*  ps     = psb + g*8;

    const float* __restrict__ Xb = X   + b*L_*D_;
    const float* __restrict__ kb = g_k + b*L_*U_;
    const float* __restrict__ qb = g_q + b*L_*U_;

    if (t < U_) reinterpret_cast<float*>(wa4)[t] = Wa[t] * 1.4426950408889634f;
    if (t < 256) {                         // q for both row-tiles (16 rows)
        int rt = t >> 7, idx = t & 127;
        int i = idx >> 4, uq = idx & 15;
        int gr = (rt ? i0B : i0A) + i;
        q_all[rt*128 + uq*8 + i] = *reinterpret_cast<const float4*>(qb + gr*U_ + uq*4);
    }

    // cp.async fill targets (tile-invariant)
    const int kf_uq0 = tl & 15,        kf_j0 = tl >> 4;
    const int kf_uq1 = (tl+256) & 15,  kf_j1 = (tl+256) >> 4;
    const unsigned k_dst0 = smem_u32(kbuf) + (kf_uq0*TJ + kf_j0)*16;
    const unsigned k_dst1 = smem_u32(kbuf) + (kf_uq1*TJ + kf_j1)*16;
    const unsigned x_dst0 = smem_u32(Xs) + tl*16;
    const unsigned KBUF_B = 512*16;    // 8KB per buffer
    const unsigned XS_B   = 8192*4;    // 32KB per buffer

    const int dp  = tl & 127;
    const int ih  = tl >> 7;
    const int ib0 = ih * 4;
    const int bid_bar = 1 + g;

    // prologue: prefetch job 0 into buffer 0
    {
        const int j0p = g ? sB*TJ : 0;
        cp16(k_dst0, kb + (j0p + kf_j0)*U_ + kf_uq0*4);
        cp16(k_dst1, kb + (j0p + kf_j1)*U_ + kf_uq1*4);
        #pragma unroll
        for (int rep = 0; rep < 8; ++rep) {
            int idx = tl + rep*256;
            cp16(x_dst0 + rep*4096, Xb + (j0p + (idx>>6))*D_ + (idx&63)*4);
        }
        cp_commit();
    }
    __syncthreads();   // wa4 + q_all visible

    float m_run = -1e30f, s_run = 0.f;
    unsigned long long acc[4] = {0ull, 0ull, 0ull, 0ull};

    for (int n = 0; n < njobs; ++n) {
        // decode current job -> (row-tile rt, j0)
        int rt, j0;
        if (g == 0) {
            if (n < ntjA) { rt = 0; j0 = n*TJ; }
            else          { rt = 1; j0 = (n - ntjA)*TJ; }
        } else            { rt = 1; j0 = (sB + n)*TJ; }
        const int cur = n & 1;

        cp_wait0();
        barg(bid_bar);   // fills visible; prev PV (readers of p4 + other buf) done

        if (n + 1 < njobs) {
            int j0n;
            if (g == 0) j0n = (n+1 < ntjA) ? (n+1)*TJ : (n+1-ntjA)*TJ;
            else        j0n = (sB + n + 1)*TJ;
            const int nxt = (n + 1) & 1;
            cp16(k_dst0 + nxt*KBUF_B, kb + (j0n + kf_j0)*U_ + kf_uq0*4);
            cp16(k_dst1 + nxt*KBUF_B, kb + (j0n + kf_j1)*U_ + kf_uq1*4);
            #pragma unroll
            for (int rep = 0; rep < 8; ++rep) {
                int idx = tl + rep*256;
                cp16(x_dst0 + nxt*XS_B + rep*4096, Xb + (j0n + (idx>>6))*D_ + (idx&63)*4);
            }
            cp_commit();
        }

        // ---- score: e[gi][j0+lane] in log2 domain ----
        const int gi = (rt ? i0B : i0A) + wl;
        const float4* kc = kbuf + cur*512;
        const float4* qr = q_all + rt*128;
        float e0 = 0.f, e1 = 0.f;
        #pragma unroll
        for (int uq = 0; uq < 16; ++uq) {
            float4 kv = kc[uq*TJ + lane];    // conflict-free
            float4 qv = qr[uq*8 + wl];       // broadcast
            float4 wa = wa4[uq];             // broadcast
            e0 += wa.x * tanh_ap(qv.x + kv.x);
            e1 += wa.y * tanh_ap(qv.y + kv.y);
            e0 += wa.z * tanh_ap(qv.z + kv.z);
            e1 += wa.w * tanh_ap(qv.w + kv.w);
        }
        float e = e0 + e1;
        if (j0 + lane > gi) e = -1e30f;   // causal: exp2 underflows to exact 0

        // ---- online softmax (warp = one row) ----
        float mt = e;
        #pragma unroll
        for (int off = 16; off; off >>= 1)
            mt = fmaxf(mt, __shfl_xor_sync(0xffffffffu, mt, off));
        float m_new = fmaxf(m_run, mt);
        float p = ex2_ap(e - m_new);
        float st = p;
        #pragma unroll
        for (int off = 16; off; off >>= 1)
            st += __shfl_xor_sync(0xffffffffu, st, off);
        float alpha = ex2_ap(m_run - m_new);
        s_run = s_run * alpha + st;
        m_run = m_new;

        const bool direct  = (g == 0) && (n + 1 == ntjA);
        const bool seg_end = direct || (n + 1 == njobs);
        p4[wl*TJ + lane] = p;
        if (lane == 0) {
            alpha_s[wl] = alpha;
            if (seg_end) {
                if (direct) sinv[wl] = 1.0f / s_run;
                else { pm[wl] = m_run; ps[wl] = s_run; }
            }
        }
        barg(bid_bar);

        // ---- PV update (packed f32x2 over d-pairs; p via LDS.128 + ALU dup) ----
        #pragma unroll
        for (int i = 0; i < 4; ++i)
            mul2(acc[i], dup2(alpha_s[ib0+i]));

        const unsigned long long* xcol =
            reinterpret_cast<const unsigned long long*>(Xs + cur*8192) + dp;
        #pragma unroll
        for (int jc = 0; jc < TJ/4; ++jc) {
            unsigned long long xv0 = xcol[(jc*4+0)*(D_/2)];
            unsigned long long xv1 = xcol[(jc*4+1)*(D_/2)];
            unsigned long long xv2 = xcol[(jc*4+2)*(D_/2)];
            unsigned long long xv3 = xcol[(jc*4+3)*(D_/2)];
            float4 pv[4];
            #pragma unroll
            for (int i = 0; i < 4; ++i)
                pv[i] = *reinterpret_cast<const float4*>(&p4[(ib0+i)*TJ + jc*4]); // broadcast
            #pragma unroll
            for (int i = 0; i < 4; ++i) {
                const float* pf = reinterpret_cast<const float*>(&pv[i]);
                fma2(acc[i], xv0, dup2(pf[0]));
                fma2(acc[i], xv1, dup2(pf[1]));
                fma2(acc[i], xv2, dup2(pf[2]));
                fma2(acc[i], xv3, dup2(pf[3]));
            }
        }

        if (seg_end) {
            if (direct) {
                // row-tile A complete: write output, reset state for B segment
                #pragma unroll
                for (int i = 0; i < 4; ++i) {
                    float2 v = unpack2(acc[i]);
                    float is = sinv[ib0 + i];
                    *reinterpret_cast<float2*>(out + (b*L_ + i0A + ib0 + i)*D_ + dp*2)
                        = make_float2(v.x*is, v.y*is);
                    acc[i] = 0ull;
                }
                m_run = -1e30f; s_run = 0.f;
            } else {
                // flush partial (unnormalized acc) for B merge
                #pragma unroll
                for (int i = 0; i < 4; ++i) {
                    float2 v = unpack2(acc[i]);
                    *reinterpret_cast<float2*>(&pacc[(ib0+i)*D_ + dp*2]) = v;
                }
            }
        }
        // no end-of-loop barrier: next iteration's top barg orders p4/buffer reuse
    }

    // ---- merge the two B partials (flash-decoding combine) ----
    __syncthreads();
    {
        const int r  = t >> 6;   // 0..7
        const int dq = t & 63;   // d-quad
        float m0 = pmb[r],  m1 = pmb[8 + r];
        float s0 = psb[r],  s1 = psb[8 + r];
        float M  = fmaxf(m0, m1);
        float w0 = ex2_ap(m0 - M), w1 = ex2_ap(m1 - M);
        float dn = 1.0f / (w0*s0 + w1*s1);
        float4 a0 = *reinterpret_cast<float4*>(&paccb[r*D_ + dq*4]);
        float4 a1 = *reinterpret_cast<float4*>(&paccb[2048 + r*D_ + dq*4]);
        float4 o;
        o.x = (w0*a0.x + w1*a1.x)*dn;
        o.y = (w0*a0.y + w1*a1.y)*dn;
        o.z = (w0*a0.z + w1*a1.z)*dn;
        o.w = (w0*a0.w + w1*a1.w)*dn;
        *reinterpret_cast<float4*>(out + (b*L_ + i0B + r)*D_ + dq*4) = o;
    }
}

// ---------------------------------------------------------------------------
extern "C" void kernel_launch(void* const* d_in, const int* in_sizes, int n_in,
                              void* d_out, int out_size)
{
    const float* X  = (const float*)d_in[0];
    const float* Wt = (const float*)d_in[1];
    const float* Wx = (const float*)d_in[2];
    const float* bh = (const float*)d_in[3];
    const float* Wa = (const float*)d_in[4];
    // d_in[5] = ba : constant shift inside softmax -> mathematically a no-op

    const int attn_smem = 2*GRP_B + 23040;   // ~182.5KB
    cudaFuncSetAttribute(attn_kernel, cudaFuncAttributeMaxDynamicSharedMemorySize, attn_smem);

    proj_kernel<<<256, 128>>>(X, Wt, Wx, bh);
    attn_kernel<<<B_*(NTROW/2), 512, attn_smem>>>(X, Wa, (float*)d_out);
}

// round 15
// speedup vs baseline: 1.2760x; 1.0428x over previous
#include <cuda_runtime.h>
#include <cstdint>

#define B_ 4
#define L_ 512
#define D_ 256
#define U_ 64
#define TI 8
#define TJ 64                      // j-tile size (doubled vs R14)
#define NTROW (L_/TI)

// scratch for projections (allowed: __device__ globals, no allocation)
__device__ float g_q[B_*L_*U_];
__device__ float g_k[B_*L_*U_];

__device__ __forceinline__ float tanh_ap(float x){ float y; asm("tanh.approx.f32 %0, %1;" : "=f"(y) : "f"(x)); return y; }
__device__ __forceinline__ float ex2_ap(float x){ float y; asm("ex2.approx.f32 %0, %1;" : "=f"(y) : "f"(x)); return y; }
__device__ __forceinline__ unsigned long long dup2(float x){
    unsigned long long r; asm("mov.b64 %0, {%1, %1};" : "=l"(r) : "f"(x)); return r;
}
__device__ __forceinline__ void fma2(unsigned long long &a, unsigned long long x, unsigned long long y){
    asm("fma.rn.f32x2 %0, %1, %2, %0;" : "+l"(a) : "l"(x), "l"(y));
}
__device__ __forceinline__ void mul2(unsigned long long &a, unsigned long long x){
    asm("mul.rn.f32x2 %0, %0, %1;" : "+l"(a) : "l"(x));
}
__device__ __forceinline__ float2 unpack2(unsigned long long v){
    float lo, hi; asm("mov.b64 {%0, %1}, %2;" : "=f"(lo), "=f"(hi) : "l"(v)); return make_float2(lo, hi);
}
__device__ __forceinline__ unsigned smem_u32(const void* p){
    return (unsigned)__cvta_generic_to_shared(p);
}
__device__ __forceinline__ void cp16(unsigned dst, const void* src){
    asm volatile("cp.async.cg.shared.global [%0], [%1], 16;" :: "r"(dst), "l"(src));
}
__device__ __forceinline__ void cp_commit(){ asm volatile("cp.async.commit_group;"); }
__device__ __forceinline__ void cp_wait0(){ asm volatile("cp.async.wait_group 0;"); }
__device__ __forceinline__ void cp_wait1(){ asm volatile("cp.async.wait_group 1;"); }
__device__ __forceinline__ void cp_wait2(){ asm volatile("cp.async.wait_group 2;"); }
__device__ __forceinline__ void barg(int id){ asm volatile("bar.sync %0, 256;" :: "r"(id) : "memory"); }

// ---------------------------------------------------------------------------
// Phase 1 (unchanged from R14 -- measured improvement): q = X@Wt ; k = X@Wx+bh
// 256 blocks x 128 threads, 16 rows/block; W in two 32KB static-smem halves;
// X direct LDG.128.
// ---------------------------------------------------------------------------
__global__ void __launch_bounds__(128) proj_kernel(
    const float* __restrict__ X, const float* __restrict__ Wt,
    const float* __restrict__ Wx, const float* __restrict__ bh)
{
    __shared__ __align__(16) float W_s[128*U_];   // 32KB (half of W)

    const int bid  = blockIdx.x;
    const bool is_k = bid >= 128;
    const int rb   = bid & 127;
    const float* __restrict__ W = is_k ? Wx : Wt;
    const int t    = threadIdx.x;
    const int row0 = rb * 16;

    const int quad = t & 15;
    const int rg   = t >> 4;

    const float4* __restrict__ Xa = reinterpret_cast<const float4*>(X + (row0+rg  )*D_);
    const float4* __restrict__ Xb = reinterpret_cast<const float4*>(X + (row0+rg+8)*D_);
    const float4* __restrict__ W4 = reinterpret_cast<const float4*>(W);

    unsigned long long a01_0 = 0ull, a23_0 = 0ull;
    unsigned long long a01_1 = 0ull, a23_1 = 0ull;

    #pragma unroll
    for (int half = 0; half < 2; ++half) {
        __syncthreads();
        #pragma unroll
        for (int i = 0; i < 16; ++i)
            reinterpret_cast<float4*>(W_s)[t + i*128] = W4[half*2048 + t + i*128];
        __syncthreads();

        const int dbase = half * 32;
        #pragma unroll 4
        for (int d4 = 0; d4 < 32; ++d4) {
            float4 xa = Xa[dbase + d4];
            float4 xb = Xb[dbase + d4];
            const float* xaf = reinterpret_cast<const float*>(&xa);
            const float* xbf = reinterpret_cast<const float*>(&xb);
            #pragma unroll
            for (int c = 0; c < 4; ++c) {
                ulonglong2 w2 = *reinterpret_cast<const ulonglong2*>(W_s + (d4*4+c)*U_ + quad*4);
                unsigned long long xx0 = dup2(xaf[c]);
                unsigned long long xx1 = dup2(xbf[c]);
                fma2(a01_0, xx0, w2.x);
                fma2(a23_0, xx0, w2.y);
                fma2(a01_1, xx1, w2.x);
                fma2(a23_1, xx1, w2.y);
            }
        }
    }

    float bx = 0.f, by = 0.f, bz = 0.f, bw = 0.f;
    if (is_k) { bx = bh[quad*4+0]; by = bh[quad*4+1]; bz = bh[quad*4+2]; bw = bh[quad*4+3]; }

    float* base = (is_k ? g_k : g_q);
    {
        float2 v01 = unpack2(a01_0), v23 = unpack2(a23_0);
        float4 o; o.x = v01.x+bx; o.y = v01.y+by; o.z = v23.x+bz; o.w = v23.y+bw;
        *reinterpret_cast<float4*>(base + (row0 + rg)*U_ + quad*4) = o;
    }
    {
        float2 v01 = unpack2(a01_1), v23 = unpack2(a23_1);
        float4 o; o.x = v01.x+bx; o.y = v01.y+by; o.z = v23.x+bz; o.w = v23.y+bw;
        *reinterpret_cast<float4*>(base + (row0 + rg + 8)*U_ + quad*4) = o;
    }
}

// ---------------------------------------------------------------------------
// Phase 2: split-KV dual-group attention, TJ=64.
// 128 CTAs x 512 threads. Pair {A=pr, B=63-pr}; 9 TJ=64 jobs split 5/4.
// k double-buffered (2x16KB); X single-buffered (64KB) with wait(2)->(1)
// choreography (fill hides under score). Sum-shuffle deferred past the
// p-store barrier (overlaps PV). B merged flash-decoding style in-kernel.
// ---------------------------------------------------------------------------
#define GRP_B (32768 + 65536)      // kbuf 2x16KB + Xs 64KB

__global__ void __launch_bounds__(512, 1) attn_kernel(
    const float* __restrict__ X, const float* __restrict__ Wa,
    float* __restrict__ out)
{
    extern __shared__ __align__(16) unsigned char smem_raw[];

    const int t    = threadIdx.x;
    const int g    = t >> 8;           // group 0/1
    const int tl   = t & 255;          // thread-in-group
    const int lane = t & 31;
    const int wl   = (t >> 5) & 7;     // warp-in-group = row
    const int b    = blockIdx.x >> 5;
    const int pr   = blockIdx.x & 31;

    const int i0A  = pr * TI;
    const int i0B  = (63 - pr) * TI;
    const int ntjA = pr/8 + 1;             // A tiles (1..4)
    const int sB   = 5 - ntjA;             // group0's B tiles [0, sB)
    const int njobs = g ? 4 : 5;

    unsigned char* grp = smem_raw + g*GRP_B;
    float4* kbuf = reinterpret_cast<float4*>(grp);                 // 2x16KB
    float*  Xs   = reinterpret_cast<float*>(grp + 32768);          // 64KB
    unsigned char* tail = smem_raw + 2*GRP_B;
    float4* q_all  = reinterpret_cast<float4*>(tail);              // 4KB
    float4* wa4    = reinterpret_cast<float4*>(tail + 4096);       // 256B
    float*  p4     = reinterpret_cast<float*>(tail + 4352) + g*512;   // 2x2KB
    float*  alpha_s= reinterpret_cast<float*>(tail + 8448) + g*8;
    float*  sinv   = reinterpret_cast<float*>(tail + 8512) + g*8;
    float*  paccb  = reinterpret_cast<float*>(tail + 8576);        // 2x8KB
    float*  pacc   = paccb + g*2048;
    float*  pmb    = reinterpret_cast<float*>(tail + 8576 + 16384);
    float*  psb    = pmb + 16;
    float*  pm     = pmb + g*8;
    float*  ps     = psb + g*8;

    const float* __restrict__ Xb = X   + b*L_*D_;
    const float* __restrict__ kb = g_k + b*L_*U_;
    const float* __restrict__ qb = g_q + b*L_*U_;

    if (t < U_) reinterpret_cast<float*>(wa4)[t] = Wa[t] * 1.4426950408889634f;
    if (t < 256) {                         // q for both row-tiles (16 rows)
        int rt = t >> 7, idx = t & 127;
        int i = idx >> 4, uq = idx & 15;
        int gr = (rt ? i0B : i0A) + i;
        q_all[rt*128 + uq*8 + i] = *reinterpret_cast<const float4*>(qb + gr*U_ + uq*4);
    }

    // cp.async targets: k layout [uq][j] (j 0..63), 4 cp16/thread per fill
    const unsigned k_base = smem_u32(kbuf);
    const unsigned x_dst0 = smem_u32(Xs) + tl*16;
    const unsigned KBUF_B = 1024*16;   // 16KB per buffer

    const int dp  = tl & 127;
    const int ih  = tl >> 7;
    const int ib0 = ih * 4;
    const int bid_bar = 1 + g;

    // prologue: prefetch k(job 0) into buffer 0
    {
        const int j0p = g ? sB*TJ : 0;
        #pragma unroll
        for (int rep = 0; rep < 4; ++rep) {
            int idx = tl + rep*256;
            int uq = idx & 15, j = idx >> 4;
            cp16(k_base + (uq*TJ + j)*16, kb + (j0p + j)*U_ + uq*4);
        }
        cp_commit();
    }
    __syncthreads();   // wa4 + q_all visible CTA-wide

    float m_run = -1e30f, s_run = 0.f;
    unsigned long long acc[4] = {0ull, 0ull, 0ull, 0ull};

    for (int n = 0; n < njobs; ++n) {
        // decode job -> (row-tile rt, j0)
        int rt, j0;
        if (g == 0) {
            if (n < ntjA) { rt = 0; j0 = n*TJ; }
            else          { rt = 1; j0 = (n - ntjA)*TJ; }
        } else            { rt = 1; j0 = (sB + n)*TJ; }
        const int cur = n & 1;
        const bool more = (n + 1 < njobs);

        barg(bid_bar);   // prev PV done reading Xs + p4

        // commit X(n) fill (64KB: 16 cp16/thread)
        #pragma unroll
        for (int rep = 0; rep < 16; ++rep) {
            int idx = tl + rep*256;
            cp16(x_dst0 + rep*4096, Xb + (j0 + (idx>>6))*D_ + (idx&63)*4);
        }
        cp_commit();
        // commit k(n+1) fill
        if (more) {
            int j0n;
            if (g == 0) j0n = (n+1 < ntjA) ? (n+1)*TJ : (n+1-ntjA)*TJ;
            else        j0n = (sB + n + 1)*TJ;
            const unsigned off = ((n+1) & 1)*KBUF_B;
            #pragma unroll
            for (int rep = 0; rep < 4; ++rep) {
                int idx = tl + rep*256;
                int uq = idx & 15, j = idx >> 4;
                cp16(k_base + off + (uq*TJ + j)*16, kb + (j0n + j)*U_ + uq*4);
            }
            cp_commit();
        }
        if (more) cp_wait2(); else cp_wait1();   // k(n) landed
        barg(bid_bar);                           // k(n) visible group-wide

        // ---- score: rows wl, j = j0+lane and j0+lane+32, log2 domain ----
        const int gi = (rt ? i0B : i0A) + wl;
        const float4* kc = kbuf + cur*1024;
        const float4* qr = q_all + rt*128;
        float e0 = 0.f, e1 = 0.f, e2 = 0.f, e3 = 0.f;
        #pragma unroll
        for (int uq = 0; uq < 16; ++uq) {
            float4 kv0 = kc[uq*TJ + lane];        // conflict-free
            float4 kv1 = kc[uq*TJ + lane + 32];   // conflict-free
            float4 qv  = qr[uq*8 + wl];           // broadcast
            float4 wa  = wa4[uq];                 // broadcast
            e0 += wa.x * tanh_ap(qv.x + kv0.x);
            e1 += wa.y * tanh_ap(qv.y + kv0.y);
            e0 += wa.z * tanh_ap(qv.z + kv0.z);
            e1 += wa.w * tanh_ap(qv.w + kv0.w);
            e2 += wa.x * tanh_ap(qv.x + kv1.x);
            e3 += wa.y * tanh_ap(qv.y + kv1.y);
            e2 += wa.z * tanh_ap(qv.z + kv1.z);
            e3 += wa.w * tanh_ap(qv.w + kv1.w);
        }
        float eA = e0 + e1;
        float eB = e2 + e3;
        if (j0 + lane      > gi) eA = -1e30f;   // causal: exp2 -> exact 0
        if (j0 + lane + 32 > gi) eB = -1e30f;

        // ---- max reduce + p (sum deferred past barrier) ----
        float mt = fmaxf(eA, eB);
        #pragma unroll
        for (int off = 16; off; off >>= 1)
            mt = fmaxf(mt, __shfl_xor_sync(0xffffffffu, mt, off));
        float m_new = fmaxf(m_run, mt);
        float p0 = ex2_ap(eA - m_new);
        float p1 = ex2_ap(eB - m_new);
        float alpha = ex2_ap(m_run - m_new);
        p4[wl*TJ + lane]      = p0;
        p4[wl*TJ + lane + 32] = p1;
        if (lane == 0) alpha_s[wl] = alpha;

        if (more) cp_wait1(); else cp_wait0();   // X(n) landed
        barg(bid_bar);                           // X + p4 + alpha visible

        // deferred sum reduction (overlaps PV issue below)
        float st = p0 + p1;
        #pragma unroll
        for (int off = 16; off; off >>= 1)
            st += __shfl_xor_sync(0xffffffffu, st, off);
        s_run = s_run * alpha + st;
        m_run = m_new;

        // ---- PV update (R14 inner form; jc now 0..15) ----
        #pragma unroll
        for (int i = 0; i < 4; ++i)
            mul2(acc[i], dup2(alpha_s[ib0+i]));

        const unsigned long long* xcol =
            reinterpret_cast<const unsigned long long*>(Xs) + dp;
        #pragma unroll
        for (int jc = 0; jc < TJ/4; ++jc) {
            unsigned long long xv0 = xcol[(jc*4+0)*(D_/2)];
            unsigned long long xv1 = xcol[(jc*4+1)*(D_/2)];
            unsigned long long xv2 = xcol[(jc*4+2)*(D_/2)];
            unsigned long long xv3 = xcol[(jc*4+3)*(D_/2)];
            float4 pv[4];
            #pragma unroll
            for (int i = 0; i < 4; ++i)
                pv[i] = *reinterpret_cast<const float4*>(&p4[(ib0+i)*TJ + jc*4]); // broadcast
            #pragma unroll
            for (int i = 0; i < 4; ++i) {
                const float* pf = reinterpret_cast<const float*>(&pv[i]);
                fma2(acc[i], xv0, dup2(pf[0]));
                fma2(acc[i], xv1, dup2(pf[1]));
                fma2(acc[i], xv2, dup2(pf[2]));
                fma2(acc[i], xv3, dup2(pf[3]));
            }
        }

        // ---- segment boundaries ----
        const bool direct  = (g == 0) && (n + 1 == ntjA);
        if (direct) {
            if (lane == 0) sinv[wl] = 1.0f / s_run;
            barg(bid_bar);              // sinv visible (only on the direct tile)
            #pragma unroll
            for (int i = 0; i < 4; ++i) {
                float2 v = unpack2(acc[i]);
                float is = sinv[ib0 + i];
                *reinterpret_cast<float2*>(out + (b*L_ + i0A + ib0 + i)*D_ + dp*2)
                    = make_float2(v.x*is, v.y*is);
                acc[i] = 0ull;
            }
            m_run = -1e30f; s_run = 0.f;
        } else if (n + 1 == njobs) {
            // flush B partial (unnormalized acc + m,s) for merge
            if (lane == 0) { pm[wl] = m_run; ps[wl] = s_run; }
            #pragma unroll
            for (int i = 0; i < 4; ++i) {
                float2 v = unpack2(acc[i]);
                *reinterpret_cast<float2*>(&pacc[(ib0+i)*D_ + dp*2]) = v;
            }
        }
        // next iteration's top barg orders p4/Xs reuse
    }

    // ---- merge the two B partials (flash-decoding combine) ----
    __syncthreads();
    {
        const int r  = t >> 6;   // 0..7
        const int dq = t & 63;   // d-quad
        float m0 = pmb[r],  m1 = pmb[8 + r];
        float s0 = psb[r],  s1 = psb[8 + r];
        float M  = fmaxf(m0, m1);
        float w0 = ex2_ap(m0 - M), w1 = ex2_ap(m1 - M);
        float dn = 1.0f / (w0*s0 + w1*s1);
        float4 a0 = *reinterpret_cast<float4*>(&paccb[r*D_ + dq*4]);
        float4 a1 = *reinterpret_cast<float4*>(&paccb[2048 + r*D_ + dq*4]);
        float4 o;
        o.x = (w0*a0.x + w1*a1.x)*dn;
        o.y = (w0*a0.y + w1*a1.y)*dn;
        o.z = (w0*a0.z + w1*a1.z)*dn;
        o.w = (w0*a0.w + w1*a1.w)*dn;
        *reinterpret_cast<float4*>(out + (b*L_ + i0B + r)*D_ + dq*4) = o;
    }
}

// ---------------------------------------------------------------------------
extern "C" void kernel_launch(void* const* d_in, const int* in_sizes, int n_in,
                              void* d_out, int out_size)
{
    const float* X  = (const float*)d_in[0];
    const float* Wt = (const float*)d_in[1];
    const float* Wx = (const float*)d_in[2];
    const float* bh = (const float*)d_in[3];
    const float* Wa = (const float*)d_in[4];
    // d_in[5] = ba : constant shift inside softmax -> mathematically a no-op

    const int attn_smem = 2*GRP_B + 25088;   // ~216.5KB
    cudaFuncSetAttribute(attn_kernel, cudaFuncAttributeMaxDynamicSharedMemorySize, attn_smem);

    proj_kernel<<<256, 128>>>(X, Wt, Wx, bh);
    attn_kernel<<<B_*(NTROW/2), 512, attn_smem>>>(X, Wa, (float*)d_out);
}